// round 9
// baseline (speedup 1.0000x reference)
#include <cuda_runtime.h>

#define NN 100000
#define L1_BLOCKS 1184   // 8 CTAs/SM target for layer1 (32-reg body)

// ---- scratch (static __device__ globals; no allocation) ----
__device__ int    g_deg[NN];             // zero at load; node_prep resets each run
__device__ float  g_dinv[NN];
__device__ float4 g_S[NN];               // layer-1 accumulator (w lane = junk)
__device__ float4 g_Q[NN];               // {sx.xyz, w-accum (init dinv)}
__device__ float  g_part[L1_BLOCKS][16]; // per-block layer-2 partials

// ---------------------------------------------------------------------------
// degree histogram over dst (self-loop added in node_prep)
__global__ void k_hist(const int* __restrict__ dst, int E) {
    int i      = blockIdx.x * blockDim.x + threadIdx.x;
    int stride = gridDim.x * blockDim.x;
    for (int e = i; e < E; e += stride) {
        atomicAdd(&g_deg[dst[e]], 1);
    }
}

// per-node: dinv = rsqrt(deg+1); Q = {dinv*x, dinv}; S = 0; reset deg
__global__ void k_node_prep(const float* __restrict__ x) {
    int v = blockIdx.x * blockDim.x + threadIdx.x;
    if (v >= NN) return;
    float d = rsqrtf((float)(g_deg[v] + 1));
    g_deg[v]  = 0;                       // deterministic across graph replays
    g_dinv[v] = d;
    g_S[v] = make_float4(0.f, 0.f, 0.f, 0.f);
    g_Q[v] = make_float4(d * x[3 * v + 0], d * x[3 * v + 1], d * x[3 * v + 2], d);
}

// fused edge pass (PROVEN 65us form), 4 divergent lanes per edge:
//   gather Q[s] (16B), gather dinv[d] (4B),
//   red.v4 S[d] += Q[s]  (w lane junk), red Q[s].w += dinv[d]
__global__ void k_scatter(const int* __restrict__ src,
                          const int* __restrict__ dst, int E) {
    int i      = blockIdx.x * blockDim.x + threadIdx.x;
    int stride = gridDim.x * blockDim.x;
    for (int e = i; e < E; e += stride) {
        int s = src[e];
        int d = dst[e];
        float4 q  = g_Q[s];              // xyz immutable this pass
        float  dd = g_dinv[d];
        asm volatile("red.global.add.v4.f32 [%0], {%1,%2,%3,%4};"
                     :: "l"(&g_S[d]), "f"(q.x), "f"(q.y), "f"(q.z), "f"(q.w)
                     : "memory");
        asm volatile("red.global.add.f32 [%0], %1;"
                     :: "l"(&((float*)&g_Q[s])[3]), "f"(dd)
                     : "memory");
    }
}

// layer-1 + layer-2 accumulation (R5 body: __ldg weights in-loop, ~32 regs),
// grid-stride with L1_BLOCKS=1184 for 8 CTAs/SM occupancy:
//   a = dinv*(S + sx);  h1 = relu(a @ W1 + b1);  acc += (w*dinv)*h1
__global__ void __launch_bounds__(256) k_layer1(const float* __restrict__ W1,
                                                const float* __restrict__ b1) {
    float acc[16];
    #pragma unroll
    for (int j = 0; j < 16; j++) acc[j] = 0.f;

    int stride = gridDim.x * blockDim.x;
    for (int v = blockIdx.x * blockDim.x + threadIdx.x; v < NN; v += stride) {
        float4 S = g_S[v];
        float4 Q = g_Q[v];
        float  d = g_dinv[v];
        float  wv = Q.w * d;
        float a0 = d * (S.x + Q.x);
        float a1 = d * (S.y + Q.y);
        float a2 = d * (S.z + Q.z);
        #pragma unroll
        for (int j = 0; j < 16; j++) {
            float h = __ldg(&b1[j])
                    + a0 * __ldg(&W1[j])
                    + a1 * __ldg(&W1[16 + j])
                    + a2 * __ldg(&W1[32 + j]);
            acc[j] += wv * fmaxf(h, 0.f);
        }
    }

    // warp reduce 16 floats
    #pragma unroll
    for (int j = 0; j < 16; j++) {
        #pragma unroll
        for (int o = 16; o > 0; o >>= 1)
            acc[j] += __shfl_down_sync(0xffffffffu, acc[j], o);
    }
    __shared__ float sm[8][16];
    int lane = threadIdx.x & 31, w = threadIdx.x >> 5;
    if (lane == 0) {
        #pragma unroll
        for (int j = 0; j < 16; j++) sm[w][j] = acc[j];
    }
    __syncthreads();
    if (threadIdx.x < 16) {
        float s = 0.f;
        #pragma unroll
        for (int ww = 0; ww < 8; ww++) s += sm[ww][threadIdx.x];
        g_part[blockIdx.x][threadIdx.x] = s;     // plain store
    }
}

// reduce partials; out[j] = (sum16/N) @ W2 + b2
__global__ void k_final(const float* __restrict__ W2, const float* __restrict__ b2,
                        float* __restrict__ out) {
    __shared__ float red[16][16];
    __shared__ float sum16[16];
    int tid = threadIdx.x;          // 256 threads
    int j = tid & 15;
    int g = tid >> 4;
    float s = 0.f;
    for (int b = g; b < L1_BLOCKS; b += 16)
        s += g_part[b][j];
    red[g][j] = s;
    __syncthreads();
    if (tid < 16) {
        float t = 0.f;
        #pragma unroll
        for (int gg = 0; gg < 16; gg++) t += red[gg][tid];
        sum16[tid] = t * (1.0f / (float)NN);
    }
    __syncthreads();
    if (tid < 32) {
        float o = __ldg(&b2[tid]);
        #pragma unroll
        for (int k = 0; k < 16; k++)
            o += sum16[k] * __ldg(&W2[k * 32 + tid]);
        out[tid] = o;
    }
}

// ---------------------------------------------------------------------------
extern "C" void kernel_launch(void* const* d_in, const int* in_sizes, int n_in,
                              void* d_out, int out_size) {
    const float* x   = (const float*)d_in[0];
    const int*   ei  = (const int*)d_in[1];
    const float* W1  = (const float*)d_in[2];
    const float* b1  = (const float*)d_in[3];
    const float* W2  = (const float*)d_in[4];
    const float* b2  = (const float*)d_in[5];
    float*       out = (float*)d_out;

    int E = in_sizes[1] / 2;
    const int* src = ei;
    const int* dst = ei + E;

    int nb_edges = (E + 255) / 256;
    if (nb_edges > 9600) nb_edges = 9600;

    k_hist<<<nb_edges, 256>>>(dst, E);
    k_node_prep<<<(NN + 255) / 256, 256>>>(x);
    k_scatter<<<nb_edges, 256>>>(src, dst, E);
    k_layer1<<<L1_BLOCKS, 256>>>(W1, b1);
    k_final<<<1, 256>>>(W2, b2, out);
}

// round 10
// speedup vs baseline: 1.1221x; 1.1221x over previous
#include <cuda_runtime.h>

#define NN 100000

// ---- scratch (static __device__ globals; no allocation) ----
__device__ int    g_deg[NN];       // atomic-only during hist; reset each run
__device__ float  g_dinv[NN];      // read-only after node_prep (dense, 400KB)
__device__ float4 g_S[NN];         // atomic-only during scatter (w lane junk)
__device__ float4 g_Q[NN];         // READ-ONLY during scatter: {sx.xyz, dinv}
__device__ float  g_w[NN];         // atomic-only during scatter: layer-2 weights
__device__ float  g_sum16[16];     // final 16-dim reduction

// ---------------------------------------------------------------------------
// degree histogram over dst; vectorized int2 index loads, 2 edges/thread
__global__ void k_hist(const int* __restrict__ dst, int E) {
    int i      = blockIdx.x * blockDim.x + threadIdx.x;
    int stride = gridDim.x * blockDim.x;
    int half   = E >> 1;
    const int2* dst2 = (const int2*)dst;
    for (int e = i; e < half; e += stride) {
        int2 d = __ldg(&dst2[e]);
        atomicAdd(&g_deg[d.x], 1);
        atomicAdd(&g_deg[d.y], 1);
    }
    if (i == 0 && (E & 1)) atomicAdd(&g_deg[dst[E - 1]], 1);
}

// per-node: dinv = rsqrt(deg+1); Q = {dinv*x, dinv}; w = dinv (self-loop);
// S = 0; reset deg; zero sum16
__global__ void k_node_prep(const float* __restrict__ x) {
    int v = blockIdx.x * blockDim.x + threadIdx.x;
    if (blockIdx.x == 0 && threadIdx.x < 16) g_sum16[threadIdx.x] = 0.f;
    if (v >= NN) return;
    float d = rsqrtf((float)(g_deg[v] + 1));
    g_deg[v]  = 0;                       // deterministic across graph replays
    g_dinv[v] = d;
    g_w[v]    = d;                       // self-loop term of layer-2 weight
    g_S[v] = make_float4(0.f, 0.f, 0.f, 0.f);
    g_Q[v] = make_float4(d * x[3 * v + 0], d * x[3 * v + 1], d * x[3 * v + 2], d);
}

// fused edge pass, 4 LTS ops/edge; Q strictly read-only, S/w strictly atomic:
//   gather Q[s] (16B), gather dinv[d] (4B),
//   red.v4 S[d] += Q[s] (w lane junk), red g_w[s] += dinv[d]
__global__ void k_scatter(const int* __restrict__ src,
                          const int* __restrict__ dst, int E) {
    int i      = blockIdx.x * blockDim.x + threadIdx.x;
    int stride = gridDim.x * blockDim.x;
    for (int e = i; e < E; e += stride) {
        int s = src[e];
        int d = dst[e];
        float4 q  = __ldg(&g_Q[s]);      // read-only array: no RMW interference
        float  dd = __ldg(&g_dinv[d]);
        asm volatile("red.global.add.v4.f32 [%0], {%1,%2,%3,%4};"
                     :: "l"(&g_S[d]), "f"(q.x), "f"(q.y), "f"(q.z), "f"(q.w)
                     : "memory");
        asm volatile("red.global.add.f32 [%0], %1;"
                     :: "l"(&g_w[s]), "f"(dd)
                     : "memory");
    }
}

// layer-1 per-node + layer-2 accumulation (R3-proven form, atomics to g_sum16):
//   a = dinv*(S + sx);  h1 = relu(a @ W1 + b1);  sum16 += (w*dinv)*h1
__global__ void k_layer1(const float* __restrict__ W1, const float* __restrict__ b1) {
    int v = blockIdx.x * blockDim.x + threadIdx.x;
    float acc[16];
    #pragma unroll
    for (int j = 0; j < 16; j++) acc[j] = 0.f;

    if (v < NN) {
        float4 S = g_S[v];
        float4 Q = g_Q[v];               // Q.w = dinv
        float  d = Q.w;
        float  wv = g_w[v] * d;
        float a0 = d * (S.x + Q.x);
        float a1 = d * (S.y + Q.y);
        float a2 = d * (S.z + Q.z);
        #pragma unroll
        for (int j = 0; j < 16; j++) {
            float h = __ldg(&b1[j])
                    + a0 * __ldg(&W1[j])
                    + a1 * __ldg(&W1[16 + j])
                    + a2 * __ldg(&W1[32 + j]);
            acc[j] = wv * fmaxf(h, 0.f);
        }
    }

    // warp reduce 16 floats, then block, then one atomic per feature per block
    #pragma unroll
    for (int j = 0; j < 16; j++) {
        #pragma unroll
        for (int o = 16; o > 0; o >>= 1)
            acc[j] += __shfl_down_sync(0xffffffffu, acc[j], o);
    }
    __shared__ float sm[8][16];
    int lane = threadIdx.x & 31, w = threadIdx.x >> 5;
    if (lane == 0) {
        #pragma unroll
        for (int j = 0; j < 16; j++) sm[w][j] = acc[j];
    }
    __syncthreads();
    if (threadIdx.x < 16) {
        float s = 0.f;
        #pragma unroll
        for (int ww = 0; ww < 8; ww++) s += sm[ww][threadIdx.x];
        atomicAdd(&g_sum16[threadIdx.x], s);
    }
}

// final: out[j] = (sum16/N) @ W2 + b2
__global__ void k_final(const float* __restrict__ W2, const float* __restrict__ b2,
                        float* __restrict__ out) {
    int j = threadIdx.x;
    if (j >= 32) return;
    float s = __ldg(&b2[j]);
    const float inv_n = 1.0f / (float)NN;
    #pragma unroll
    for (int k = 0; k < 16; k++)
        s += (g_sum16[k] * inv_n) * __ldg(&W2[k * 32 + j]);
    out[j] = s;
}

// ---------------------------------------------------------------------------
extern "C" void kernel_launch(void* const* d_in, const int* in_sizes, int n_in,
                              void* d_out, int out_size) {
    const float* x   = (const float*)d_in[0];
    const int*   ei  = (const int*)d_in[1];
    const float* W1  = (const float*)d_in[2];
    const float* b1  = (const float*)d_in[3];
    const float* W2  = (const float*)d_in[4];
    const float* b2  = (const float*)d_in[5];
    float*       out = (float*)d_out;

    int E = in_sizes[1] / 2;
    const int* src = ei;
    const int* dst = ei + E;

    int nb_nodes = (NN + 255) / 256;
    int nb_hist  = ((E / 2) + 255) / 256;
    if (nb_hist > 9600) nb_hist = 9600;
    int nb_scat  = (E + 255) / 256;
    if (nb_scat > 9600) nb_scat = 9600;

    k_hist<<<nb_hist, 256>>>(dst, E);
    k_node_prep<<<nb_nodes, 256>>>(x);
    k_scatter<<<nb_scat, 256>>>(src, dst, E);
    k_layer1<<<nb_nodes, 256>>>(W1, b1);
    k_final<<<1, 32>>>(W2, b2, out);
}